// round 16
// baseline (speedup 1.0000x reference)
#include <cuda_runtime.h>
#include <math.h>

#define NTOK 8192
#define HDIM 4096
#define NOUT 12       // M_ANCH * (D+1)
#define NANCH 4
#define KOUT 16

// GEMM decomposition (rounding-order-mandated): 2 contiguous chunks of 2048.
#define KC 2048
#define HT 32                        // k per tile
#define NT (KC / HT)                 // 64 tiles
#define TOKB 128                     // tokens per block
#define TPB 384                      // 3 threads per token (j-split by 4)
#define NSTAGE 7
#define ROWB 144                     // bytes per token row (128 data + 16 pad)
#define W_BYTES (KC * 48)            // [k][12] 48B rows = 98304
#define TILE_BYTES (TOKB * ROWB)     // 18432
#define SMEM_TOTAL (W_BYTES + NSTAGE * TILE_BYTES)   // 227328 (within 228KB)

extern "C" __device__ float __nv_expf(float);

// chunk partial sums: g_part[chunk][token][j]
__device__ float g_part[2][NTOK][NOUT];

// ---------------------------------------------------------------------------
// XLA f32 tanh (EmitFastTanh), bit-exact — frozen since round 5.
// ---------------------------------------------------------------------------
__device__ __forceinline__ float xla_tanhf(float x) {
    const float plus_clamp = 7.90531110763549805f;
    const float ax = fabsf(x);
    const float xc = fmaxf(fminf(x, plus_clamp), -plus_clamp);
    const float x2 = __fmul_rn(xc, xc);
    float p = fmaf(x2, -2.76076847742355e-16f, 2.00018790482477e-13f);
    p = fmaf(x2, p, -8.60467152213735e-11f);
    p = fmaf(x2, p, 5.12229709037114e-08f);
    p = fmaf(x2, p, 1.48572235717979e-05f);
    p = fmaf(x2, p, 6.37261928875436e-04f);
    p = fmaf(x2, p, 4.89352455891786e-03f);
    p = __fmul_rn(xc, p);
    float q = fmaf(x2, 1.19825839466702e-06f, 1.18534705686654e-04f);
    q = fmaf(x2, q, 2.26843463243900e-03f);
    q = fmaf(x2, q, 4.89352518554385e-03f);
    return (ax < 0.0004f) ? x : __fdiv_rn(p, q);
}
__device__ __forceinline__ float xla_sigmoidf(float x) {
    const float t = xla_tanhf(__fmul_rn(0.5f, x));
    return __fadd_rn(__fmul_rn(0.5f, t), 0.5f);
}

// ---------------------------------------------------------------------------
// One k, 4 outputs (js quarter-of-12): 1 LDS.v2.b64 + 2 FFMA2.
// Per-lane IEEE f32x2 fma chains, ascending k — identical per-(token,j)
// rounding sequence to the passing kernels.
// ---------------------------------------------------------------------------
__device__ __forceinline__ void fma_k(float h, unsigned wk,
                                      unsigned long long& a0,
                                      unsigned long long& a1) {
    asm("{\n\t"
        ".reg .b64 hd, w0, w1;\n\t"
        "mov.b64 hd, {%2, %2};\n\t"
        "ld.shared.v2.b64 {w0, w1}, [%3];\n\t"
        "fma.rn.f32x2 %0, hd, w0, %0;\n\t"
        "fma.rn.f32x2 %1, hd, w1, %1;\n\t"
        "}"
        : "+l"(a0), "+l"(a1)
        : "f"(h), "r"(wk));
}

// ---------------------------------------------------------------------------
// Kernel 1: per-chunk partial logits. 3 threads/token (4 outputs each),
// 12 warps. W k-major [k][12] in smem (warp-uniform 16B broadcast reads).
// Hidden staged via 16B cp.async into padded row-major tiles (ROWB=144,
// conflict-free STS/LDS.128), 7-stage pipeline, ONE barrier per tile
// (stage of slot (t-1)%7 happens after the barrier that proves t-1 done).
// Ascending-k fma chain unchanged (bit-exact).
// ---------------------------------------------------------------------------
__global__ __launch_bounds__(TPB, 1)
void logits_kernel(const float* __restrict__ hidden,
                   const float* __restrict__ W) {
    extern __shared__ float sm[];
    const int tid   = threadIdx.x;
    const int chunk = blockIdx.y;
    const int kc    = chunk * KC;
    const int tok0  = blockIdx.x * TOKB;
    const unsigned sb = (unsigned)__cvta_generic_to_shared(sm);
    const unsigned tb = sb + W_BYTES;

#define STAGE(T, SLOT) do {                                                  \
    const int _t = (T);                                                      \
    const unsigned dst0 = tb + (unsigned)(SLOT) * TILE_BYTES;                \
    const float* src0 = hidden + (size_t)tok0 * HDIM + kc + _t * HT;         \
    _Pragma("unroll")                                                        \
    for (int r = 0; r < 3; ++r) {                                            \
        const int s = tid + r * TPB;                                         \
        if (s < 1024) {                                                      \
            const int tok = s >> 3, p = s & 7;                               \
            const float* src = src0 + (size_t)tok * HDIM + p * 4;            \
            const unsigned dst = dst0 + tok * ROWB + p * 16;                 \
            asm volatile("cp.async.ca.shared.global [%0], [%1], 16;"         \
                         :: "r"(dst), "l"(src));                             \
        }                                                                    \
    }                                                                        \
    asm volatile("cp.async.commit_group;");                                  \
} while (0)

    STAGE(0, 0); STAGE(1, 1); STAGE(2, 2);
    STAGE(3, 3); STAGE(4, 4); STAGE(5, 5);

    // W preload: sm[k*12 + j] = W[j][kc+k], coalesced global reads.
    for (int i = tid; i < KC * 12; i += TPB) {
        const int j = i >> 11;                // 0..11
        const int k = i & (KC - 1);
        sm[k * 12 + j] = W[(size_t)j * HDIM + kc + k];
    }

    const int js = tid >> 7;                  // 0..2: outputs 4js..4js+3
    const int lt = tid & 127;                 // local token
    const unsigned wb   = sb + js * 16;       // W base, +48B per k
    const unsigned hrow = tb + lt * ROWB;

    unsigned long long a0 = 0ull, a1 = 0ull;

    int slot = 0;       // slot of tile t
    int nslot = 6;      // slot where tile t+6 goes
    for (int t = 0; t < NT; ++t) {
        const int rem = NT - 1 - t;           // groups still pending past t
        if (rem >= 5)      asm volatile("cp.async.wait_group 5;");
        else switch (rem) {
            case 4: asm volatile("cp.async.wait_group 4;"); break;
            case 3: asm volatile("cp.async.wait_group 3;"); break;
            case 2: asm volatile("cp.async.wait_group 2;"); break;
            case 1: asm volatile("cp.async.wait_group 1;"); break;
            default: asm volatile("cp.async.wait_group 0;"); break;
        }
        __syncthreads();   // tile t visible to all; tile t-1 fully consumed

        if (t + 6 < NT) STAGE(t + 6, nslot);  // overwrites slot of t-1: safe

        // my 128B h row for this tile -> registers (8 x LDS.128)
        const unsigned hb = hrow + (unsigned)slot * TILE_BYTES;
        float4 hq[8];
#pragma unroll
        for (int p = 0; p < 8; ++p) {
            asm("ld.shared.v4.f32 {%0,%1,%2,%3}, [%4];"
                : "=f"(hq[p].x), "=f"(hq[p].y), "=f"(hq[p].z), "=f"(hq[p].w)
                : "r"(hb + p * 16));
        }

        unsigned wk = wb + (unsigned)(t * HT) * 48;
#pragma unroll
        for (int p = 0; p < 8; ++p) {
            fma_k(hq[p].x, wk,       a0, a1);
            fma_k(hq[p].y, wk + 48,  a0, a1);
            fma_k(hq[p].z, wk + 96,  a0, a1);
            fma_k(hq[p].w, wk + 144, a0, a1);
            wk += 192;
        }

        if (++slot == NSTAGE) slot = 0;
        if (++nslot == NSTAGE) nslot = 0;
    }
#undef STAGE

    float4 o;
    o.x = __uint_as_float((unsigned)(a0 & 0xffffffffull));
    o.y = __uint_as_float((unsigned)(a0 >> 32));
    o.z = __uint_as_float((unsigned)(a1 & 0xffffffffull));
    o.w = __uint_as_float((unsigned)(a1 >> 32));
    *(float4*)&g_part[chunk][tok0 + lt][js * 4] = o;
}

// ---------------------------------------------------------------------------
// Kernel 2: per-token routing epilogue, one warp per token (proven, 20us).
// Folds chunk partials ((0+p0)+p1)+b — exact passing rounding sequence.
// ---------------------------------------------------------------------------
__device__ __forceinline__ unsigned int ford(float v) {
    unsigned int u = __float_as_uint(v);
    return (u & 0x80000000u) ? ~u : (u | 0x80000000u);
}

__global__ __launch_bounds__(256, 8)
void route_kernel(const float* __restrict__ b, float* __restrict__ out) {
    const int lane  = threadIdx.x & 31;
    const int token = blockIdx.x * (blockDim.x >> 5) + (threadIdx.x >> 5);
    if (token >= NTOK) return;

    float lg = 0.f;
    if (lane < NOUT) {
        const float p0 = g_part[0][token][lane];
        const float p1 = g_part[1][token][lane];
        lg = __fadd_rn(__fadd_rn(__fadd_rn(0.0f, p0), p1), b[lane]);
    }
    float L[NOUT];
#pragma unroll
    for (int i = 0; i < NOUT; ++i) L[i] = __shfl_sync(0xffffffffu, lg, i);

    // anchor softmax over L[2], L[5], L[8], L[11]
    float pi[NANCH];
    {
        const float m = fmaxf(fmaxf(L[2], L[5]), fmaxf(L[8], L[11]));
        const float e0 = __nv_expf(__fadd_rn(L[2], -m));
        const float e1 = __nv_expf(__fadd_rn(L[5], -m));
        const float e2 = __nv_expf(__fadd_rn(L[8], -m));
        const float e3 = __nv_expf(__fadd_rn(L[11], -m));
        const float s = __fadd_rn(__fadd_rn(__fadd_rn(e0, e1), e2), e3);
        pi[0] = __fdiv_rn(e0, s); pi[1] = __fdiv_rn(e1, s);
        pi[2] = __fdiv_rn(e2, s); pi[3] = __fdiv_rn(e3, s);
    }

    float v0 = 0.f, v1 = 0.f;   // my two cells: lane, lane+32

#pragma unroll
    for (int a = 0; a < NANCH; ++a) {
        float fr[2]; int ai[2];
#pragma unroll
        for (int d = 0; d < 2; ++d) {
            const float x = L[a * 3 + d];
            float u = xla_sigmoidf(x);
            u = fminf(fmaxf(u, 1e-6f), 1.0f - 1e-6f);
            float p = __fmul_rn(u, 7.0f);
            p = fminf(p, 7.0f - 1e-6f);
            p = fmaxf(p, 0.f);
            int aa = (int)floorf(p);
            aa = max(0, min(aa, 6));
            float f = __fadd_rn(p, -(float)aa);
            f = fminf(fmaxf(f, 1e-6f), 1.0f - 1e-6f);
            fr[d] = f; ai[d] = aa;
        }
        const float om0 = __fadd_rn(1.0f, -fr[0]);
        const float om1 = __fadd_rn(1.0f, -fr[1]);
        float w[4];
        w[0] = __fmul_rn(om0,   om1);
        w[1] = __fmul_rn(fr[0], om1);
        w[2] = __fmul_rn(om0,   fr[1]);
        w[3] = __fmul_rn(fr[0], fr[1]);
        const float ws = __fadd_rn(__fadd_rn(__fadd_rn(w[0], w[1]), w[2]), w[3]);
        const float denom = __fadd_rn(ws, 1e-9f);
#pragma unroll
        for (int t = 0; t < 4; ++t) {
            const int c0 = ai[0] + (t & 1);
            const int c1 = ai[1] + ((t >> 1) & 1);
            const int idx = c0 + (c1 << 3);
            const float wv = __fmul_rn(__fdiv_rn(w[t], denom), pi[a]);
            if (idx == lane)      v0 = __fadd_rn(v0, wv);
            if (idx == lane + 32) v1 = __fadd_rn(v1, wv);
        }
    }

    // normalize by grid sum (common denominator: cannot flip ranks)
    float s = __fadd_rn(v0, v1);
    s = __fadd_rn(s, __shfl_xor_sync(0xffffffffu, s, 16));
    s = __fadd_rn(s, __shfl_xor_sync(0xffffffffu, s, 8));
    s = __fadd_rn(s, __shfl_xor_sync(0xffffffffu, s, 4));
    s = __fadd_rn(s, __shfl_xor_sync(0xffffffffu, s, 2));
    s = __fadd_rn(s, __shfl_xor_sync(0xffffffffu, s, 1));
    const float dn = __fadd_rn(s, 1e-9f);
    v0 = __fdiv_rn(v0, dn);
    v1 = __fdiv_rn(v1, dn);

    float* out_idx = out + (size_t)token * KOUT;
    float* out_w   = out + (size_t)NTOK * KOUT + (size_t)token * KOUT;

    for (int r = 0; r < KOUT; ++r) {
        unsigned long long k0 =
            ((unsigned long long)ford(v0) << 32) | (unsigned int)(63 - lane);
        unsigned long long k1 =
            ((unsigned long long)ford(v1) << 32) | (unsigned int)(63 - (lane + 32));
        unsigned long long k = (k0 > k1) ? k0 : k1;
#pragma unroll
        for (int sft = 16; sft > 0; sft >>= 1) {
            unsigned long long o = __shfl_xor_sync(0xffffffffu, k, sft);
            if (o > k) k = o;
        }
        const int cell = 63 - (int)(k & 63ull);
        const unsigned int ou = (unsigned int)(k >> 32);
        const float val =
            __uint_as_float((ou & 0x80000000u) ? (ou ^ 0x80000000u) : ~ou);
        if (lane == 0) {
            out_idx[r] = (float)cell;
            out_w[r]   = val;
        }
        if (cell == lane)      v0 = -1.0f;
        if (cell == lane + 32) v1 = -1.0f;
    }
}

// ---------------------------------------------------------------------------
extern "C" void kernel_launch(void* const* d_in, const int* in_sizes, int n_in,
                              void* d_out, int out_size) {
    const float* hidden = nullptr;
    const float* W = nullptr;
    const float* b = nullptr;
    for (int i = 0; i < n_in; ++i) {
        if (in_sizes[i] == NTOK * HDIM)      hidden = (const float*)d_in[i];
        else if (in_sizes[i] == NOUT * HDIM) W = (const float*)d_in[i];
        else if (in_sizes[i] == NOUT)        b = (const float*)d_in[i];
    }
    (void)out_size;

    cudaFuncSetAttribute(logits_kernel,
                         cudaFuncAttributeMaxDynamicSharedMemorySize, SMEM_TOTAL);
    dim3 grid(NTOK / TOKB, 2);
    logits_kernel<<<grid, TPB, SMEM_TOTAL>>>(hidden, W);
    route_kernel<<<NTOK / 8, 256>>>(b, (float*)d_out);
}

// round 17
// speedup vs baseline: 1.1095x; 1.1095x over previous
#include <cuda_runtime.h>
#include <math.h>

#define NTOK 8192
#define HDIM 4096
#define NOUT 12       // M_ANCH * (D+1)
#define NANCH 4
#define KOUT 16

// GEMM decomposition (rounding-order-mandated): 2 contiguous chunks of 2048.
#define KC 2048
#define HT 32                        // k per tile
#define NT (KC / HT)                 // 64 tiles
#define TOKB 128                     // tokens per block
#define TPB 256                      // 2 threads per token (jh split)
#define NSTAGE 7
#define ROWB 144                     // bytes per token row (128 data + 16 pad)
#define W_BYTES (KC * 48)            // [k][12] 48B rows = 98304
#define TILE_BYTES (TOKB * ROWB)     // 18432
#define SMEM_TOTAL (W_BYTES + NSTAGE * TILE_BYTES)   // 227328

extern "C" __device__ float __nv_expf(float);

// chunk partial sums: g_part[chunk][token][j]
__device__ float g_part[2][NTOK][NOUT];

// ---------------------------------------------------------------------------
// XLA f32 tanh (EmitFastTanh), bit-exact — frozen since round 5.
// ---------------------------------------------------------------------------
__device__ __forceinline__ float xla_tanhf(float x) {
    const float plus_clamp = 7.90531110763549805f;
    const float ax = fabsf(x);
    const float xc = fmaxf(fminf(x, plus_clamp), -plus_clamp);
    const float x2 = __fmul_rn(xc, xc);
    float p = fmaf(x2, -2.76076847742355e-16f, 2.00018790482477e-13f);
    p = fmaf(x2, p, -8.60467152213735e-11f);
    p = fmaf(x2, p, 5.12229709037114e-08f);
    p = fmaf(x2, p, 1.48572235717979e-05f);
    p = fmaf(x2, p, 6.37261928875436e-04f);
    p = fmaf(x2, p, 4.89352455891786e-03f);
    p = __fmul_rn(xc, p);
    float q = fmaf(x2, 1.19825839466702e-06f, 1.18534705686654e-04f);
    q = fmaf(x2, q, 2.26843463243900e-03f);
    q = fmaf(x2, q, 4.89352518554385e-03f);
    return (ax < 0.0004f) ? x : __fdiv_rn(p, q);
}
__device__ __forceinline__ float xla_sigmoidf(float x) {
    const float t = xla_tanhf(__fmul_rn(0.5f, x));
    return __fadd_rn(__fmul_rn(0.5f, t), 0.5f);
}

// ---------------------------------------------------------------------------
// Identical fused-fma chain step as the passing kernel (bit-exact order).
// ---------------------------------------------------------------------------
__device__ __forceinline__ void fma_step(float h, unsigned addr,
                                         unsigned long long& a0,
                                         unsigned long long& a1,
                                         unsigned long long& a2) {
    asm("{\n\t"
        ".reg .b64 hd, w0, w1, w2;\n\t"
        "mov.b64 hd, {%3, %3};\n\t"
        "ld.shared.b64 w0, [%4];\n\t"
        "ld.shared.b64 w1, [%4+8];\n\t"
        "ld.shared.b64 w2, [%4+16];\n\t"
        "fma.rn.f32x2 %0, hd, w0, %0;\n\t"
        "fma.rn.f32x2 %1, hd, w1, %1;\n\t"
        "fma.rn.f32x2 %2, hd, w2, %2;\n\t"
        "}"
        : "+l"(a0), "+l"(a1), "+l"(a2)
        : "f"(h), "r"(addr));
}

// ---------------------------------------------------------------------------
// Kernel 1: R13 structure (proven fastest) + 7-stage pipeline and ONE
// barrier per tile (tile t+6 staged after the barrier that proves t-1
// consumed; it overwrites slot (t-1)%7). jh split, W k-major [k][12],
// ROWB=144 conflict-free staging. Ascending-k fma chain bit-exact.
// ---------------------------------------------------------------------------
__global__ __launch_bounds__(TPB, 1)
void logits_kernel(const float* __restrict__ hidden,
                   const float* __restrict__ W) {
    extern __shared__ float sm[];
    const int tid   = threadIdx.x;
    const int chunk = blockIdx.y;
    const int kc    = chunk * KC;
    const int tok0  = blockIdx.x * TOKB;
    const unsigned sb = (unsigned)__cvta_generic_to_shared(sm);
    const unsigned tb = sb + W_BYTES;

#define STAGE(T, SLOT) do {                                                  \
    const int _t = (T);                                                      \
    const unsigned dst0 = tb + (unsigned)(SLOT) * TILE_BYTES;                \
    const float* src0 = hidden + (size_t)tok0 * HDIM + kc + _t * HT;         \
    _Pragma("unroll")                                                        \
    for (int r = 0; r < 4; ++r) {                                            \
        const int s = tid + r * TPB;                                         \
        const int tok = s >> 3, p = s & 7;                                   \
        const float* src = src0 + (size_t)tok * HDIM + p * 4;                \
        const unsigned dst = dst0 + tok * ROWB + p * 16;                     \
        asm volatile("cp.async.ca.shared.global [%0], [%1], 16;"             \
                     :: "r"(dst), "l"(src));                                 \
    }                                                                        \
    asm volatile("cp.async.commit_group;");                                  \
} while (0)

    STAGE(0, 0); STAGE(1, 1); STAGE(2, 2);
    STAGE(3, 3); STAGE(4, 4); STAGE(5, 5);

    // W preload: sm[k*12 + j] = W[j][kc+k], coalesced global reads.
    for (int i = tid; i < KC * 12; i += TPB) {
        const int j = i >> 11;                // 0..11
        const int k = i & (KC - 1);
        sm[k * 12 + j] = W[(size_t)j * HDIM + kc + k];
    }

    const int jh = tid & 1;                   // which 6 outputs
    const int lt = tid >> 1;                  // local token 0..127
    const unsigned wb   = sb + jh * 24;       // W base, +48B per k
    const unsigned hrow = tb + lt * ROWB;

    unsigned long long a0 = 0ull, a1 = 0ull, a2 = 0ull;

    int slot = 0;       // slot of tile t
    int nslot = 6;      // slot where tile t+6 goes
    for (int t = 0; t < NT; ++t) {
        const int rem = NT - 1 - t;
        if (rem >= 5)      asm volatile("cp.async.wait_group 5;");
        else switch (rem) {
            case 4: asm volatile("cp.async.wait_group 4;"); break;
            case 3: asm volatile("cp.async.wait_group 3;"); break;
            case 2: asm volatile("cp.async.wait_group 2;"); break;
            case 1: asm volatile("cp.async.wait_group 1;"); break;
            default: asm volatile("cp.async.wait_group 0;"); break;
        }
        __syncthreads();   // tile t visible; tile t-1 fully consumed

        if (t + 6 < NT) STAGE(t + 6, nslot);  // overwrites slot of t-1: safe

        const unsigned hb = hrow + (unsigned)slot * TILE_BYTES;
        float4 hq[8];
#pragma unroll
        for (int p = 0; p < 8; ++p) {
            asm("ld.shared.v4.f32 {%0,%1,%2,%3}, [%4];"
                : "=f"(hq[p].x), "=f"(hq[p].y), "=f"(hq[p].z), "=f"(hq[p].w)
                : "r"(hb + p * 16));
        }

        unsigned wk = wb + (unsigned)(t * HT) * 48;
#pragma unroll
        for (int p = 0; p < 8; ++p) {
            fma_step(hq[p].x, wk,       a0, a1, a2);
            fma_step(hq[p].y, wk + 48,  a0, a1, a2);
            fma_step(hq[p].z, wk + 96,  a0, a1, a2);
            fma_step(hq[p].w, wk + 144, a0, a1, a2);
            wk += 192;
        }

        if (++slot == NSTAGE) slot = 0;
        if (++nslot == NSTAGE) nslot = 0;
    }
#undef STAGE

    const int gt = tok0 + lt;
    float2* pd = (float2*)&g_part[chunk][gt][jh * 6];
    pd[0] = *(float2*)&a0;
    pd[1] = *(float2*)&a1;
    pd[2] = *(float2*)&a2;
}

// ---------------------------------------------------------------------------
// Kernel 2: per-token routing epilogue, one warp per token.
// Candidate-parallel front-end: lane computes candidate (lane&15) only
// (a = cand>>2, t = cand&3). Scatter into per-lane cells (v0: cell=lane,
// v1: cell=lane+32) via a 16-step shuffle broadcast in ascending candidate
// order — the exact reference scatter-add order. Per-anchor denominator
// folded sequentially w0..w3; logit fold, softmax, tie-break unchanged.
// Selection: keys built once, winner cleared by key equality (sentinel 0).
// ---------------------------------------------------------------------------
__device__ __forceinline__ unsigned int ford(float v) {
    unsigned int u = __float_as_uint(v);
    return (u & 0x80000000u) ? ~u : (u | 0x80000000u);
}

__global__ __launch_bounds__(256, 8)
void route_kernel(const float* __restrict__ b, float* __restrict__ out) {
    const int lane  = threadIdx.x & 31;
    const int token = blockIdx.x * (blockDim.x >> 5) + (threadIdx.x >> 5);
    if (token >= NTOK) return;

    float lg = 0.f;
    if (lane < NOUT) {
        const float p0 = g_part[0][token][lane];
        const float p1 = g_part[1][token][lane];
        lg = __fadd_rn(__fadd_rn(__fadd_rn(0.0f, p0), p1), b[lane]);
    }
    float L[NOUT];
#pragma unroll
    for (int i = 0; i < NOUT; ++i) L[i] = __shfl_sync(0xffffffffu, lg, i);

    // anchor softmax over L[2], L[5], L[8], L[11] (all lanes)
    float pi[NANCH];
    {
        const float m = fmaxf(fmaxf(L[2], L[5]), fmaxf(L[8], L[11]));
        const float e0 = __nv_expf(__fadd_rn(L[2], -m));
        const float e1 = __nv_expf(__fadd_rn(L[5], -m));
        const float e2 = __nv_expf(__fadd_rn(L[8], -m));
        const float e3 = __nv_expf(__fadd_rn(L[11], -m));
        const float s = __fadd_rn(__fadd_rn(__fadd_rn(e0, e1), e2), e3);
        pi[0] = __fdiv_rn(e0, s); pi[1] = __fdiv_rn(e1, s);
        pi[2] = __fdiv_rn(e2, s); pi[3] = __fdiv_rn(e3, s);
    }

    // my candidate: cand = lane & 15; a = cand >> 2; t = cand & 3
    const int cand = lane & 15;
    const int a    = cand >> 2;
    const int t    = cand & 3;
    int   my_idx;
    float my_wv;
    {
        float fr[2]; int ai[2];
#pragma unroll
        for (int d = 0; d < 2; ++d) {
            const float x = (d == 0) ? L[a * 3] : L[a * 3 + 1];
            float u = xla_sigmoidf(x);
            u = fminf(fmaxf(u, 1e-6f), 1.0f - 1e-6f);
            float p = __fmul_rn(u, 7.0f);
            p = fminf(p, 7.0f - 1e-6f);
            p = fmaxf(p, 0.f);
            int aa = (int)floorf(p);
            aa = max(0, min(aa, 6));
            float f = __fadd_rn(p, -(float)aa);
            f = fminf(fmaxf(f, 1e-6f), 1.0f - 1e-6f);
            fr[d] = f; ai[d] = aa;
        }
        const float om0 = __fadd_rn(1.0f, -fr[0]);
        const float om1 = __fadd_rn(1.0f, -fr[1]);
        float w[4];
        w[0] = __fmul_rn(om0,   om1);
        w[1] = __fmul_rn(fr[0], om1);
        w[2] = __fmul_rn(om0,   fr[1]);
        w[3] = __fmul_rn(fr[0], fr[1]);
        const float ws = __fadd_rn(__fadd_rn(__fadd_rn(w[0], w[1]), w[2]), w[3]);
        const float denom = __fadd_rn(ws, 1e-9f);
        const float wt = (t == 0) ? w[0] : (t == 1) ? w[1] : (t == 2) ? w[2] : w[3];
        const int c0 = ai[0] + (t & 1);
        const int c1 = ai[1] + ((t >> 1) & 1);
        my_idx = c0 + (c1 << 3);
        my_wv  = __fmul_rn(__fdiv_rn(wt, denom), pi[a]);
    }

    // scatter in ascending candidate order (reference order)
    float v0 = 0.f, v1 = 0.f;
#pragma unroll
    for (int c = 0; c < 16; ++c) {
        const int   bi = __shfl_sync(0xffffffffu, my_idx, c);
        const float bw = __shfl_sync(0xffffffffu, my_wv, c);
        if (bi == lane)      v0 = __fadd_rn(v0, bw);
        if (bi == lane + 32) v1 = __fadd_rn(v1, bw);
    }

    // normalize by grid sum (common denominator: cannot flip ranks)
    float s = __fadd_rn(v0, v1);
    s = __fadd_rn(s, __shfl_xor_sync(0xffffffffu, s, 16));
    s = __fadd_rn(s, __shfl_xor_sync(0xffffffffu, s, 8));
    s = __fadd_rn(s, __shfl_xor_sync(0xffffffffu, s, 4));
    s = __fadd_rn(s, __shfl_xor_sync(0xffffffffu, s, 2));
    s = __fadd_rn(s, __shfl_xor_sync(0xffffffffu, s, 1));
    const float dn = __fadd_rn(s, 1e-9f);
    v0 = __fdiv_rn(v0, dn);
    v1 = __fdiv_rn(v1, dn);

    // keys built once; winner cleared by key equality (all live keys > 0)
    unsigned long long k0 =
        ((unsigned long long)ford(v0) << 32) | (unsigned int)(63 - lane);
    unsigned long long k1 =
        ((unsigned long long)ford(v1) << 32) | (unsigned int)(63 - (lane + 32));

    float oi[KOUT], ow[KOUT];
#pragma unroll
    for (int r = 0; r < KOUT; ++r) {
        unsigned long long k = (k0 > k1) ? k0 : k1;
#pragma unroll
        for (int sft = 16; sft > 0; sft >>= 1) {
            unsigned long long o = __shfl_xor_sync(0xffffffffu, k, sft);
            if (o > k) k = o;
        }
        const int cell = 63 - (int)(k & 63ull);
        const unsigned int ou = (unsigned int)(k >> 32);
        oi[r] = (float)cell;
        ow[r] = __uint_as_float((ou & 0x80000000u) ? (ou ^ 0x80000000u) : ~ou);
        if (k0 == k) k0 = 0ull;
        if (k1 == k) k1 = 0ull;
    }

    if (lane == 0) {
        float4* out_idx = (float4*)(out + (size_t)token * KOUT);
        float4* out_w   = (float4*)(out + (size_t)NTOK * KOUT + (size_t)token * KOUT);
#pragma unroll
        for (int v = 0; v < 4; ++v) {
            out_idx[v] = make_float4(oi[v*4], oi[v*4+1], oi[v*4+2], oi[v*4+3]);
            out_w[v]   = make_float4(ow[v*4], ow[v*4+1], ow[v*4+2], ow[v*4+3]);
        }
    }
}

// ---------------------------------------------------------------------------
extern "C" void kernel_launch(void* const* d_in, const int* in_sizes, int n_in,
                              void* d_out, int out_size) {
    const float* hidden = nullptr;
    const float* W = nullptr;
    const float* b = nullptr;
    for (int i = 0; i < n_in; ++i) {
        if (in_sizes[i] == NTOK * HDIM)      hidden = (const float*)d_in[i];
        else if (in_sizes[i] == NOUT * HDIM) W = (const float*)d_in[i];
        else if (in_sizes[i] == NOUT)        b = (const float*)d_in[i];
    }
    (void)out_size;

    cudaFuncSetAttribute(logits_kernel,
                         cudaFuncAttributeMaxDynamicSharedMemorySize, SMEM_TOTAL);
    dim3 grid(NTOK / TOKB, 2);
    logits_kernel<<<grid, TPB, SMEM_TOTAL>>>(hidden, W);
    route_kernel<<<NTOK / 8, 256>>>(b, (float*)d_out);
}